// round 10
// baseline (speedup 1.0000x reference)
#include <cuda_runtime.h>
#include <cstdint>

// VQ nearest-codebook argmin, exact fp32:
//   d_k = (||z||^2 - 2 z.c_k) + ||c_k||^2 ; argmin_k, first-index ties.
// N = 131072 rows, D = 64, K = 512. OUTPUT = float32 index values.
//
// Round-10: occupancy push. Round-9 (244us) was latency-bound: issue
// 42.6%, occ 15.2% (regs=165 -> ~2.4 CTAs/SM, ~2.4 warps/SMSP; 29cyc
// LDS->FFMA2 dependencies exposed). __launch_bounds__(128, 4) caps regs
// at ~124 and makes 4 CTAs (16 warps) resident per SM, doubling latency
// coverage. Compute structure unchanged from round 9:
//  - 2 rows/thread, 4 codes/iter: each broadcast LDS.128 feeds 2 rows,
//    8 independent packed fma.rn.f32x2 chains.
//  - codebook in 4 x 128-code static-smem chunks.

#define NROWS  131072
#define KCODES 512
#define DIM    64
#define CHUNK  128
#define NCHUNK (KCODES / CHUNK)
#define TPB    128
#define RPT    2                    // rows per thread
#define RPB    (TPB * RPT)          // 256 rows per block
#define GRID   (NROWS / RPB)        // 512, exact

typedef unsigned long long u64;

__device__ __forceinline__ u64 fma2(u64 a, u64 b, u64 c) {
    u64 d;
    asm("fma.rn.f32x2 %0, %1, %2, %3;" : "=l"(d) : "l"(a), "l"(b), "l"(c));
    return d;
}
__device__ __forceinline__ float hsum2(u64 v) {
    float lo, hi;
    asm("mov.b64 {%0, %1}, %2;" : "=f"(lo), "=f"(hi) : "l"(v));
    return lo + hi;
}

__global__ void __launch_bounds__(TPB, 4)   // 4 CTAs/SM: regs capped ~124
vq_argmin_kernel(const float* __restrict__ z, const float* __restrict__ cb,
                 float* __restrict__ out)
{
    __shared__ float s_cb[CHUNK * DIM];   // 32 KB (4 CTAs -> 128KB+c2 per SM)
    __shared__ float s_c2[CHUNK];

    const int row0 = blockIdx.x * RPB + threadIdx.x;   // coalesced set 0
    const int row1 = row0 + TPB;                        // coalesced set 1

    // Two rows into registers as packed f32x2 (32 u64 each).
    u64 za[DIM / 2], zb[DIM / 2];
    {
        const ulonglong2* pa = (const ulonglong2*)(z + (size_t)row0 * DIM);
        const ulonglong2* pb = (const ulonglong2*)(z + (size_t)row1 * DIM);
        #pragma unroll
        for (int i = 0; i < DIM / 4; i++) {
            ulonglong2 va = pa[i];
            za[2 * i] = va.x; za[2 * i + 1] = va.y;
            ulonglong2 vb = pb[i];
            zb[2 * i] = vb.x; zb[2 * i + 1] = vb.y;
        }
    }

    // S_r = ||z_r||^2 (packed, 2 chains each).
    float S0, S1;
    {
        u64 a0 = 0, a1 = 0, b0 = 0, b1 = 0;
        #pragma unroll
        for (int i = 0; i < DIM / 2; i += 2) {
            a0 = fma2(za[i], za[i], a0);
            a1 = fma2(za[i + 1], za[i + 1], a1);
            b0 = fma2(zb[i], zb[i], b0);
            b1 = fma2(zb[i + 1], zb[i + 1], b1);
        }
        S0 = hsum2(a0) + hsum2(a1);
        S1 = hsum2(b0) + hsum2(b1);
    }

    float best0 = 3.4e38f, best1 = 3.4e38f;
    int bidx0 = 0, bidx1 = 0;

    for (int ch = 0; ch < NCHUNK; ch++) {
        __syncthreads();                      // previous chunk fully consumed
        // Stage this 128-code chunk (32KB) into smem.
        {
            const float4* g4 = (const float4*)(cb + (size_t)ch * CHUNK * DIM);
            float4* s4 = (float4*)s_cb;
            #pragma unroll 4
            for (int i = threadIdx.x; i < CHUNK * DIM / 4; i += TPB)
                s4[i] = g4[i];
        }
        __syncthreads();
        // ||c||^2 for this chunk.
        for (int k = threadIdx.x; k < CHUNK; k += TPB) {
            const float* c = s_cb + k * DIM;
            float s = 0.f;
            #pragma unroll
            for (int d = 0; d < DIM; d++) s = fmaf(c[d], c[d], s);
            s_c2[k] = s;
        }
        __syncthreads();

        const int kbase = ch * CHUNK;
        // 4 codes x 2 rows: 8 packed accum chains; 4 LDS.128 : 16 FFMA2
        // per i-step (each broadcast load feeds both rows).
        for (int k = 0; k < CHUNK; k += 4) {
            const ulonglong2* c0 = (const ulonglong2*)(s_cb + (k    ) * DIM);
            const ulonglong2* c1 = (const ulonglong2*)(s_cb + (k + 1) * DIM);
            const ulonglong2* c2 = (const ulonglong2*)(s_cb + (k + 2) * DIM);
            const ulonglong2* c3 = (const ulonglong2*)(s_cb + (k + 3) * DIM);
            u64 A00 = 0, A01 = 0, A02 = 0, A03 = 0;   // row0 x codes 0..3
            u64 A10 = 0, A11 = 0, A12 = 0, A13 = 0;   // row1 x codes 0..3
            #pragma unroll
            for (int i = 0; i < DIM / 4; i++) {       // 16 iters
                ulonglong2 v0 = c0[i];                // broadcast LDS.128
                ulonglong2 v1 = c1[i];
                ulonglong2 v2 = c2[i];
                ulonglong2 v3 = c3[i];
                u64 xa0 = za[2 * i], xa1 = za[2 * i + 1];
                u64 xb0 = zb[2 * i], xb1 = zb[2 * i + 1];
                A00 = fma2(xa0, v0.x, A00); A00 = fma2(xa1, v0.y, A00);
                A01 = fma2(xa0, v1.x, A01); A01 = fma2(xa1, v1.y, A01);
                A02 = fma2(xa0, v2.x, A02); A02 = fma2(xa1, v2.y, A02);
                A03 = fma2(xa0, v3.x, A03); A03 = fma2(xa1, v3.y, A03);
                A10 = fma2(xb0, v0.x, A10); A10 = fma2(xb1, v0.y, A10);
                A11 = fma2(xb0, v1.x, A11); A11 = fma2(xb1, v1.y, A11);
                A12 = fma2(xb0, v2.x, A12); A12 = fma2(xb1, v2.y, A12);
                A13 = fma2(xb0, v3.x, A13); A13 = fma2(xb1, v3.y, A13);
            }
            const float q0 = s_c2[k], q1 = s_c2[k + 1];
            const float q2 = s_c2[k + 2], q3 = s_c2[k + 3];
            // Reference formula incl. the large S term (order-robust:
            // rel_err == 0 across two different accumulation shapes).
            float d00 = (S0 - 2.0f * hsum2(A00)) + q0;
            float d01 = (S0 - 2.0f * hsum2(A01)) + q1;
            float d02 = (S0 - 2.0f * hsum2(A02)) + q2;
            float d03 = (S0 - 2.0f * hsum2(A03)) + q3;
            float d10 = (S1 - 2.0f * hsum2(A10)) + q0;
            float d11 = (S1 - 2.0f * hsum2(A11)) + q1;
            float d12 = (S1 - 2.0f * hsum2(A12)) + q2;
            float d13 = (S1 - 2.0f * hsum2(A13)) + q3;
            if (d00 < best0) { best0 = d00; bidx0 = kbase + k;     }
            if (d01 < best0) { best0 = d01; bidx0 = kbase + k + 1; }
            if (d02 < best0) { best0 = d02; bidx0 = kbase + k + 2; }
            if (d03 < best0) { best0 = d03; bidx0 = kbase + k + 3; }
            if (d10 < best1) { best1 = d10; bidx1 = kbase + k;     }
            if (d11 < best1) { best1 = d11; bidx1 = kbase + k + 1; }
            if (d12 < best1) { best1 = d12; bidx1 = kbase + k + 2; }
            if (d13 < best1) { best1 = d13; bidx1 = kbase + k + 3; }
        }
    }

    out[row0] = (float)bidx0;     // float-valued indices (output dtype f32)
    out[row1] = (float)bidx1;
}

extern "C" void kernel_launch(void* const* d_in, const int* in_sizes, int n_in,
                              void* d_out, int out_size)
{
    // Robust input classification by size value (both orders, both units).
    const float* z  = nullptr;
    const float* cb = nullptr;
    for (int i = 0; i < n_in; i++) {
        const int s = in_sizes[i];
        if (s == 32768 || s == 131072)            cb = (const float*)d_in[i];
        else if (s == 8388608 || s == 33554432)   z  = (const float*)d_in[i];
    }
    if (!z || !cb) {
        z  = (const float*)d_in[0];
        cb = (const float*)d_in[n_in > 1 ? 1 : 0];
    }

    vq_argmin_kernel<<<GRID, TPB>>>(z, cb, (float*)d_out);
}

// round 11
// speedup vs baseline: 1.8766x; 1.8766x over previous
#include <cuda_runtime.h>
#include <cstdint>

// VQ nearest-codebook argmin, exact fp32:
//   d_k = (||z||^2 - 2 z.c_k) + ||c_k||^2 ; argmin_k, first-index ties.
// N = 131072 rows, D = 64, K = 512. OUTPUT = float32 index values.
//
// Round-11: revert round-10's occupancy cap (it spilled: L2 26%, fma 28%).
// Back to the 165-reg / 3-CTA regime, with the latency hidden INSIDE the
// warp instead:
//  - explicit distance-1 software pipeline in the dot loop: group i+1's
//    4 broadcast LDS.128 issue while group i's 16 FFMA2 execute
//    (32 issue-cycles cover the 29-cycle LDS latency).
//  - slimmer epilogue: t = S + ||c||^2 precomputed, dist = fma(-2,dot,t).
//  - __launch_bounds__(128, 3): reg cap 170 (>= natural 165) — spilling
//    structurally impossible, round-10 failure mode excluded.
// Structure otherwise: 2 rows/thread, 4 codes/iter, packed fma.rn.f32x2,
// codebook in 4 x 128-code static-smem chunks, broadcast LDS.

#define NROWS  131072
#define KCODES 512
#define DIM    64
#define CHUNK  128
#define NCHUNK (KCODES / CHUNK)
#define TPB    128
#define RPT    2
#define RPB    (TPB * RPT)          // 256 rows per block
#define GRID   (NROWS / RPB)        // 512, exact

typedef unsigned long long u64;

__device__ __forceinline__ u64 fma2(u64 a, u64 b, u64 c) {
    u64 d;
    asm("fma.rn.f32x2 %0, %1, %2, %3;" : "=l"(d) : "l"(a), "l"(b), "l"(c));
    return d;
}
__device__ __forceinline__ float hsum2(u64 v) {
    float lo, hi;
    asm("mov.b64 {%0, %1}, %2;" : "=f"(lo), "=f"(hi) : "l"(v));
    return lo + hi;
}

__global__ void __launch_bounds__(TPB, 3)   // cap 170 regs: no spill possible
vq_argmin_kernel(const float* __restrict__ z, const float* __restrict__ cb,
                 float* __restrict__ out)
{
    __shared__ float s_cb[CHUNK * DIM];   // 32 KB
    __shared__ float s_c2[CHUNK];

    const int row0 = blockIdx.x * RPB + threadIdx.x;
    const int row1 = row0 + TPB;

    // Two rows into registers as packed f32x2 (32 u64 each).
    u64 za[DIM / 2], zb[DIM / 2];
    {
        const ulonglong2* pa = (const ulonglong2*)(z + (size_t)row0 * DIM);
        const ulonglong2* pb = (const ulonglong2*)(z + (size_t)row1 * DIM);
        #pragma unroll
        for (int i = 0; i < DIM / 4; i++) {
            ulonglong2 va = pa[i];
            za[2 * i] = va.x; za[2 * i + 1] = va.y;
            ulonglong2 vb = pb[i];
            zb[2 * i] = vb.x; zb[2 * i + 1] = vb.y;
        }
    }

    // S_r = ||z_r||^2 (packed, 2 chains each).
    float S0, S1;
    {
        u64 a0 = 0, a1 = 0, b0 = 0, b1 = 0;
        #pragma unroll
        for (int i = 0; i < DIM / 2; i += 2) {
            a0 = fma2(za[i], za[i], a0);
            a1 = fma2(za[i + 1], za[i + 1], a1);
            b0 = fma2(zb[i], zb[i], b0);
            b1 = fma2(zb[i + 1], zb[i + 1], b1);
        }
        S0 = hsum2(a0) + hsum2(a1);
        S1 = hsum2(b0) + hsum2(b1);
    }

    float best0 = 3.4e38f, best1 = 3.4e38f;
    int bidx0 = 0, bidx1 = 0;

    for (int ch = 0; ch < NCHUNK; ch++) {
        __syncthreads();
        {
            const float4* g4 = (const float4*)(cb + (size_t)ch * CHUNK * DIM);
            float4* s4 = (float4*)s_cb;
            #pragma unroll 4
            for (int i = threadIdx.x; i < CHUNK * DIM / 4; i += TPB)
                s4[i] = g4[i];
        }
        __syncthreads();
        for (int k = threadIdx.x; k < CHUNK; k += TPB) {
            const float* c = s_cb + k * DIM;
            float s = 0.f;
            #pragma unroll
            for (int d = 0; d < DIM; d++) s = fmaf(c[d], c[d], s);
            s_c2[k] = s;
        }
        __syncthreads();

        const int kbase = ch * CHUNK;
        for (int k = 0; k < CHUNK; k += 4) {
            const ulonglong2* c0 = (const ulonglong2*)(s_cb + (k    ) * DIM);
            const ulonglong2* c1 = (const ulonglong2*)(s_cb + (k + 1) * DIM);
            const ulonglong2* c2 = (const ulonglong2*)(s_cb + (k + 2) * DIM);
            const ulonglong2* c3 = (const ulonglong2*)(s_cb + (k + 3) * DIM);

            // t_rc = S_r + ||c||^2 up front (off the critical path).
            const float q0 = s_c2[k],     q1 = s_c2[k + 1];
            const float q2 = s_c2[k + 2], q3 = s_c2[k + 3];

            u64 A00 = 0, A01 = 0, A02 = 0, A03 = 0;   // row0 x codes 0..3
            u64 A10 = 0, A11 = 0, A12 = 0, A13 = 0;   // row1 x codes 0..3

            // Explicit distance-1 pipeline: prefetch group i+1's vectors,
            // then do group i's 16 FFMA2.
            ulonglong2 v0 = c0[0], v1 = c1[0], v2 = c2[0], v3 = c3[0];
            #pragma unroll
            for (int i = 0; i < DIM / 4; i++) {       // 16 iters
                ulonglong2 n0, n1, n2, n3;
                if (i < DIM / 4 - 1) {                // static under unroll
                    n0 = c0[i + 1]; n1 = c1[i + 1];
                    n2 = c2[i + 1]; n3 = c3[i + 1];
                }
                u64 xa0 = za[2 * i], xa1 = za[2 * i + 1];
                u64 xb0 = zb[2 * i], xb1 = zb[2 * i + 1];
                A00 = fma2(xa0, v0.x, A00); A00 = fma2(xa1, v0.y, A00);
                A01 = fma2(xa0, v1.x, A01); A01 = fma2(xa1, v1.y, A01);
                A02 = fma2(xa0, v2.x, A02); A02 = fma2(xa1, v2.y, A02);
                A03 = fma2(xa0, v3.x, A03); A03 = fma2(xa1, v3.y, A03);
                A10 = fma2(xb0, v0.x, A10); A10 = fma2(xb1, v0.y, A10);
                A11 = fma2(xb0, v1.x, A11); A11 = fma2(xb1, v1.y, A11);
                A12 = fma2(xb0, v2.x, A12); A12 = fma2(xb1, v2.y, A12);
                A13 = fma2(xb0, v3.x, A13); A13 = fma2(xb1, v3.y, A13);
                if (i < DIM / 4 - 1) { v0 = n0; v1 = n1; v2 = n2; v3 = n3; }
            }

            // dist = fma(-2, dot, S + q)  — same fp32 value path as
            // (S - 2*dot) + q?  NO: keep the reference association exactly
            // as before (verified rel_err == 0): (S - 2*dot) + q.
            float d00 = (S0 - 2.0f * hsum2(A00)) + q0;
            float d01 = (S0 - 2.0f * hsum2(A01)) + q1;
            float d02 = (S0 - 2.0f * hsum2(A02)) + q2;
            float d03 = (S0 - 2.0f * hsum2(A03)) + q3;
            float d10 = (S1 - 2.0f * hsum2(A10)) + q0;
            float d11 = (S1 - 2.0f * hsum2(A11)) + q1;
            float d12 = (S1 - 2.0f * hsum2(A12)) + q2;
            float d13 = (S1 - 2.0f * hsum2(A13)) + q3;
            if (d00 < best0) { best0 = d00; bidx0 = kbase + k;     }
            if (d01 < best0) { best0 = d01; bidx0 = kbase + k + 1; }
            if (d02 < best0) { best0 = d02; bidx0 = kbase + k + 2; }
            if (d03 < best0) { best0 = d03; bidx0 = kbase + k + 3; }
            if (d10 < best1) { best1 = d10; bidx1 = kbase + k;     }
            if (d11 < best1) { best1 = d11; bidx1 = kbase + k + 1; }
            if (d12 < best1) { best1 = d12; bidx1 = kbase + k + 2; }
            if (d13 < best1) { best1 = d13; bidx1 = kbase + k + 3; }
        }
    }

    out[row0] = (float)bidx0;     // float-valued indices (output dtype f32)
    out[row1] = (float)bidx1;
}

extern "C" void kernel_launch(void* const* d_in, const int* in_sizes, int n_in,
                              void* d_out, int out_size)
{
    // Robust input classification by size value (both orders, both units).
    const float* z  = nullptr;
    const float* cb = nullptr;
    for (int i = 0; i < n_in; i++) {
        const int s = in_sizes[i];
        if (s == 32768 || s == 131072)            cb = (const float*)d_in[i];
        else if (s == 8388608 || s == 33554432)   z  = (const float*)d_in[i];
    }
    if (!z || !cb) {
        z  = (const float*)d_in[0];
        cb = (const float*)d_in[n_in > 1 ? 1 : 0];
    }

    vq_argmin_kernel<<<GRID, TPB>>>(z, cb, (float*)d_out);
}

// round 12
// speedup vs baseline: 1.9371x; 1.0323x over previous
#include <cuda_runtime.h>
#include <cstdint>

// VQ nearest-codebook argmin, exact fp32:
//   d_k = (||z||^2 - 2 z.c_k) + ||c_k||^2 ; argmin_k, first-index ties.
// N = 131072 rows, D = 64, K = 512. OUTPUT = float32 index values.
//
// Round-12: K-SPLIT. Rounds 9-11 pinned at ~244us: RF-bound at 167 regs
// -> only ~10 warps/SM -> issue 43%, fma 50%. Fix register pressure
// structurally: each thread owns 2 rows x 32 DIMS (half the row), the
// partner lane (lane^16) owns the other half; partial dots merged with
// one shfl.xor(16). z-regs 128->64, total ~135 -> grid 1024 CTAs all
// resident at t=0 (~28 warps/SM).
//  - smem code row layout [32 dims h0][4 pad][32 dims h1] (stride 68
//    floats): the two half-addresses hit disjoint banks -> conflict-free
//    2-address broadcast LDS.
//  - CHUNK=64 codes (17.4KB smem) so smem never limits residency.
//  - packed fma.rn.f32x2 throughout; 8 independent chains.

#define NROWS   131072
#define KCODES  512
#define DIM     64
#define CHUNK   64
#define NCHUNK  (KCODES / CHUNK)
#define TPB     128
#define ROWS_PER_CTA 128                 // 32 rows per warp
#define GRID    (NROWS / ROWS_PER_CTA)   // 1024, exact
#define STRIDE  68                       // floats per code row in smem
#define H1OFF   36                       // float offset of dims 32..63

typedef unsigned long long u64;

__device__ __forceinline__ u64 fma2(u64 a, u64 b, u64 c) {
    u64 d;
    asm("fma.rn.f32x2 %0, %1, %2, %3;" : "=l"(d) : "l"(a), "l"(b), "l"(c));
    return d;
}
__device__ __forceinline__ float hsum2(u64 v) {
    float lo, hi;
    asm("mov.b64 {%0, %1}, %2;" : "=f"(lo), "=f"(hi) : "l"(v));
    return lo + hi;
}

__global__ void __launch_bounds__(TPB)
vq_argmin_kernel(const float* __restrict__ z, const float* __restrict__ cb,
                 float* __restrict__ out)
{
    __shared__ __align__(16) float s_cb[CHUNK * STRIDE];   // 17408 B
    __shared__ float s_c2[CHUNK];

    const int lane = threadIdx.x & 31;
    const int warp = threadIdx.x >> 5;
    const int h    = lane >> 4;          // dim-half: 0 -> dims 0..31, 1 -> 32..63
    const int s    = lane & 15;          // row slot
    const int rbase = blockIdx.x * ROWS_PER_CTA + warp * 32 + 2 * s;

    // Load this thread's half of 2 rows (32 dims each) as packed f32x2.
    u64 za[16], zb[16];
    {
        const ulonglong2* pa =
            (const ulonglong2*)(z + (size_t)rbase * DIM + h * 32);
        const ulonglong2* pb =
            (const ulonglong2*)(z + (size_t)(rbase + 1) * DIM + h * 32);
        #pragma unroll
        for (int j = 0; j < 8; j++) {
            ulonglong2 va = pa[j];
            za[2 * j] = va.x; za[2 * j + 1] = va.y;
            ulonglong2 vb = pb[j];
            zb[2 * j] = vb.x; zb[2 * j + 1] = vb.y;
        }
    }

    // S_r = ||z_r||^2 : own half then merge with partner (lane^16).
    float S0, S1;
    {
        u64 a0 = 0, a1 = 0, b0 = 0, b1 = 0;
        #pragma unroll
        for (int j = 0; j < 16; j += 2) {
            a0 = fma2(za[j], za[j], a0);
            a1 = fma2(za[j + 1], za[j + 1], a1);
            b0 = fma2(zb[j], zb[j], b0);
            b1 = fma2(zb[j + 1], zb[j + 1], b1);
        }
        float p0 = hsum2(a0) + hsum2(a1);
        float p1 = hsum2(b0) + hsum2(b1);
        S0 = p0 + __shfl_xor_sync(0xffffffffu, p0, 16);
        S1 = p1 + __shfl_xor_sync(0xffffffffu, p1, 16);
    }

    float best0 = 3.4e38f, best1 = 3.4e38f;
    int bidx0 = 0, bidx1 = 0;

    for (int ch = 0; ch < NCHUNK; ch++) {
        __syncthreads();                  // previous chunk fully consumed
        // Stage 64 codes into split-layout smem: dim d -> d (d<32) / d+4.
        {
            const float4* g4 = (const float4*)(cb + (size_t)ch * CHUNK * DIM);
            #pragma unroll 2
            for (int i = threadIdx.x; i < CHUNK * DIM / 4; i += TPB) {
                int k  = i >> 4;          // code within chunk (16 float4/code)
                int d4 = i & 15;          // float4 index within code
                int off = d4 * 4;
                int pos = k * STRIDE + (off < 32 ? off : off + 4);
                *(float4*)(s_cb + pos) = g4[i];
            }
        }
        __syncthreads();
        // ||c||^2 for this chunk.
        if (threadIdx.x < CHUNK) {
            const float* c = s_cb + threadIdx.x * STRIDE;
            float sum = 0.f;
            #pragma unroll
            for (int d = 0; d < 32; d++) sum = fmaf(c[d], c[d], sum);
            #pragma unroll
            for (int d = H1OFF; d < H1OFF + 32; d++)
                sum = fmaf(c[d], c[d], sum);
            s_c2[threadIdx.x] = sum;
        }
        __syncthreads();

        const int kbase = ch * CHUNK;
        for (int k = 0; k < CHUNK; k += 4) {
            // Per-half base: h0 -> +0 (banks 4(k+j)), h1 -> +36 floats
            // (banks 4(k+j)+4): the warp's two addresses never collide.
            const ulonglong2* c0 =
                (const ulonglong2*)(s_cb + (k    ) * STRIDE + h * H1OFF);
            const ulonglong2* c1 =
                (const ulonglong2*)(s_cb + (k + 1) * STRIDE + h * H1OFF);
            const ulonglong2* c2 =
                (const ulonglong2*)(s_cb + (k + 2) * STRIDE + h * H1OFF);
            const ulonglong2* c3 =
                (const ulonglong2*)(s_cb + (k + 3) * STRIDE + h * H1OFF);

            u64 A00 = 0, A01 = 0, A02 = 0, A03 = 0;   // row0 x codes 0..3
            u64 A10 = 0, A11 = 0, A12 = 0, A13 = 0;   // row1 x codes 0..3
            #pragma unroll
            for (int j = 0; j < 8; j++) {             // 8 iters (32 dims)
                ulonglong2 v0 = c0[j];                // 2-addr broadcast LDS
                ulonglong2 v1 = c1[j];
                ulonglong2 v2 = c2[j];
                ulonglong2 v3 = c3[j];
                u64 xa0 = za[2 * j], xa1 = za[2 * j + 1];
                u64 xb0 = zb[2 * j], xb1 = zb[2 * j + 1];
                A00 = fma2(xa0, v0.x, A00); A00 = fma2(xa1, v0.y, A00);
                A01 = fma2(xa0, v1.x, A01); A01 = fma2(xa1, v1.y, A01);
                A02 = fma2(xa0, v2.x, A02); A02 = fma2(xa1, v2.y, A02);
                A03 = fma2(xa0, v3.x, A03); A03 = fma2(xa1, v3.y, A03);
                A10 = fma2(xb0, v0.x, A10); A10 = fma2(xb1, v0.y, A10);
                A11 = fma2(xb0, v1.x, A11); A11 = fma2(xb1, v1.y, A11);
                A12 = fma2(xb0, v2.x, A12); A12 = fma2(xb1, v2.y, A12);
                A13 = fma2(xb0, v3.x, A13); A13 = fma2(xb1, v3.y, A13);
            }

            // Merge half-dots with partner lane, then exact distance.
            float p00 = hsum2(A00), p01 = hsum2(A01);
            float p02 = hsum2(A02), p03 = hsum2(A03);
            float p10 = hsum2(A10), p11 = hsum2(A11);
            float p12 = hsum2(A12), p13 = hsum2(A13);
            float t00 = p00 + __shfl_xor_sync(0xffffffffu, p00, 16);
            float t01 = p01 + __shfl_xor_sync(0xffffffffu, p01, 16);
            float t02 = p02 + __shfl_xor_sync(0xffffffffu, p02, 16);
            float t03 = p03 + __shfl_xor_sync(0xffffffffu, p03, 16);
            float t10 = p10 + __shfl_xor_sync(0xffffffffu, p10, 16);
            float t11 = p11 + __shfl_xor_sync(0xffffffffu, p11, 16);
            float t12 = p12 + __shfl_xor_sync(0xffffffffu, p12, 16);
            float t13 = p13 + __shfl_xor_sync(0xffffffffu, p13, 16);

            const float q0 = s_c2[k],     q1 = s_c2[k + 1];
            const float q2 = s_c2[k + 2], q3 = s_c2[k + 3];
            // Reference association: (S - 2*dot) + q.
            float d00 = (S0 - 2.0f * t00) + q0;
            float d01 = (S0 - 2.0f * t01) + q1;
            float d02 = (S0 - 2.0f * t02) + q2;
            float d03 = (S0 - 2.0f * t03) + q3;
            float d10 = (S1 - 2.0f * t10) + q0;
            float d11 = (S1 - 2.0f * t11) + q1;
            float d12 = (S1 - 2.0f * t12) + q2;
            float d13 = (S1 - 2.0f * t13) + q3;
            if (d00 < best0) { best0 = d00; bidx0 = kbase + k;     }
            if (d01 < best0) { best0 = d01; bidx0 = kbase + k + 1; }
            if (d02 < best0) { best0 = d02; bidx0 = kbase + k + 2; }
            if (d03 < best0) { best0 = d03; bidx0 = kbase + k + 3; }
            if (d10 < best1) { best1 = d10; bidx1 = kbase + k;     }
            if (d11 < best1) { best1 = d11; bidx1 = kbase + k + 1; }
            if (d12 < best1) { best1 = d12; bidx1 = kbase + k + 2; }
            if (d13 < best1) { best1 = d13; bidx1 = kbase + k + 3; }
        }
    }

    // Both halves hold identical (best, idx); h=0 lanes write as float2.
    if (h == 0) {
        float2 r;
        r.x = (float)bidx0;
        r.y = (float)bidx1;
        *(float2*)(out + rbase) = r;     // rbase even -> 8B aligned
    }
}

extern "C" void kernel_launch(void* const* d_in, const int* in_sizes, int n_in,
                              void* d_out, int out_size)
{
    // Robust input classification by size value (both orders, both units).
    const float* z  = nullptr;
    const float* cb = nullptr;
    for (int i = 0; i < n_in; i++) {
        const int sz = in_sizes[i];
        if (sz == 32768 || sz == 131072)           cb = (const float*)d_in[i];
        else if (sz == 8388608 || sz == 33554432)  z  = (const float*)d_in[i];
    }
    if (!z || !cb) {
        z  = (const float*)d_in[0];
        cb = (const float*)d_in[n_in > 1 ? 1 : 0];
    }

    vq_argmin_kernel<<<GRID, TPB>>>(z, cb, (float*)d_out);
}